// round 11
// baseline (speedup 1.0000x reference)
#include <cuda_runtime.h>
#include <cuda_fp16.h>
#include <cstdint>

// dw[p][q] = LR * ( (1/B)*sum_b post[b][p]*pre[b][q] - WD*W[p][q] )
// B=128, P=Q=1024.  fp16 single-pass mma.sync (rel err ~3e-5).
// R11: single launch. Phase A: each of 128 co-resident CTAs converts 1/128 of
// pre/post fp32->fp16 into gmem staging (layout-preserving) while W prefetch
// LDGs drain. Software grid barrier (atomic counter; grid=128 <= 148 SMs so
// all CTAs resident -> no deadlock; counter advances by exactly 128 per run).
// Phase B: verified R10 GEMM: cp.async fp16 [k][m] tiles + ldmatrix.x4.trans,
// fused weight-decay epilogue.

#define DIM      1024
#define KDIM     128
#define NTHREADS 512
#define BM       128
#define BN       64
#define NCTAS    128

#define PA       272                  // A tile row pitch bytes
#define PB       144                  // B tile row pitch bytes
#define FA       0
#define FB       (KDIM * PA)          // 34816
#define SMEM_TOTAL (FB + KDIM * PB)   // 53248

__device__ __align__(16) __half g_postH[KDIM * DIM];
__device__ __align__(16) __half g_preH [KDIM * DIM];
__device__ int g_cnt;                  // zero-initialized at module load

static __device__ __forceinline__ uint32_t smem_u32(const void* p) {
    uint32_t a;
    asm("{ .reg .u64 t; cvta.to.shared.u64 t, %1; cvt.u32.u64 %0, t; }" : "=r"(a) : "l"(p));
    return a;
}
static __device__ __forceinline__ void cp16(uint32_t saddr, const void* gaddr) {
    asm volatile("cp.async.ca.shared.global [%0], [%1], 16;" :: "r"(saddr), "l"(gaddr));
}
static __device__ __forceinline__ void ldsm_x4_trans(uint32_t* r, uint32_t addr) {
    asm volatile("ldmatrix.sync.aligned.m8n8.x4.trans.shared.b16 {%0,%1,%2,%3}, [%4];"
                 : "=r"(r[0]), "=r"(r[1]), "=r"(r[2]), "=r"(r[3]) : "r"(addr));
}
static __device__ __forceinline__ void mma16816(float* c, const uint32_t* a,
                                                uint32_t b0, uint32_t b1) {
    asm volatile(
        "mma.sync.aligned.m16n8k16.row.col.f32.f16.f16.f32 "
        "{%0,%1,%2,%3}, {%4,%5,%6,%7}, {%8,%9}, {%0,%1,%2,%3};"
        : "+f"(c[0]), "+f"(c[1]), "+f"(c[2]), "+f"(c[3])
        : "r"(a[0]), "r"(a[1]), "r"(a[2]), "r"(a[3]), "r"(b0), "r"(b1));
}
static __device__ __forceinline__ uint32_t pack_h2(float a, float b) {
    const __half2 h = __floats2half2_rn(a, b);
    return *(const uint32_t*)&h;
}

__global__ __launch_bounds__(NTHREADS, 1)
void hebbian_fused_kernel(const float* __restrict__ pre,
                          const float* __restrict__ post,
                          const float* __restrict__ W,
                          float* __restrict__ out)
{
    extern __shared__ char smem[];
    const uint32_t sbase = smem_u32(smem);
    const int tid  = threadIdx.x;
    const int lane = tid & 31;
    const int wid  = tid >> 5;
    const int pm0  = blockIdx.y * BM;
    const int qn0  = blockIdx.x * BN;
    const int cta  = blockIdx.y * 16 + blockIdx.x;

    // warp tiling: 8(m) x 2(n), warp tile m16 x n32
    const int wm = (wid >> 1) * 16;
    const int wn = (wid & 1) * 32;
    const int prow = pm0 + wm + (lane >> 2);
    const int qcol = qn0 + wn + (lane & 3) * 2;

    // ---- W prefetch (DRAM-cold; drains during convert + barrier) ----
    float2 wv[4][2];
    #pragma unroll
    for (int nn = 0; nn < 4; ++nn) {
        const int q = qcol + nn * 8;
        wv[nn][0] = *(const float2*)(W + (size_t)prow * DIM + q);
        wv[nn][1] = *(const float2*)(W + (size_t)(prow + 8) * DIM + q);
    }

    // ---- phase A: convert this CTA's 1/128 share, fp32 -> fp16 ----
    // 32768 8-float units total; 256 units/CTA (threads 0..255).
    if (tid < 256) {
        const int n = KDIM * DIM / 8;                   // 16384 units per tensor
        const int u = cta * 256 + tid;
        const bool isPost = (u >= n);
        const float4* src = (const float4*)(isPost ? post : pre);
        __half* dst = isPost ? g_postH : g_preH;
        const int i = isPost ? (u - n) : u;
        const float4 v0 = src[i * 2];
        const float4 v1 = src[i * 2 + 1];
        uint4 o;
        o.x = pack_h2(v0.x, v0.y); o.y = pack_h2(v0.z, v0.w);
        o.z = pack_h2(v1.x, v1.y); o.w = pack_h2(v1.z, v1.w);
        ((uint4*)dst)[i] = o;
        __threadfence();                                 // publish before arrive
    }
    __syncthreads();

    // ---- software grid barrier (all 128 CTAs resident) ----
    if (tid == 0) {
        const int old  = atomicAdd(&g_cnt, 1);
        const int goal = (old / NCTAS) * NCTAS + NCTAS;
        while (atomicAdd(&g_cnt, 0) < goal) { }
    }
    __syncthreads();
    __threadfence();                                     // acquire staged data

    // ---- phase B: cp.async fp16 [k][m] tiles into smem ----
    #pragma unroll
    for (int it = 0; it < 4; ++it) {              // A: 128 rows x 16 chunks
        const int c = tid + NTHREADS * it;
        const int k = c >> 4;
        const int f = (c & 15);
        cp16(sbase + FA + k * PA + f * 16, g_postH + (size_t)k * DIM + pm0 + f * 8);
    }
    #pragma unroll
    for (int it = 0; it < 2; ++it) {              // B: 128 rows x 8 chunks
        const int c = tid + NTHREADS * it;
        const int k = c >> 3;
        const int f = (c & 7);
        cp16(sbase + FB + k * PB + f * 16, g_preH + (size_t)k * DIM + qn0 + f * 8);
    }
    asm volatile("cp.async.commit_group;\n\tcp.async.wait_group 0;" ::: "memory");
    __syncthreads();

    float acc[4][4];
    #pragma unroll
    for (int j = 0; j < 4; ++j)
        #pragma unroll
        for (int r = 0; r < 4; ++r)
            acc[j][r] = 0.0f;

    const int kl = (lane & 7) + ((lane >> 4) << 3);   // k row within 16-block
    const int ml = (lane & 8);                        // m/n sub-tile select

    #pragma unroll
    for (int ks = 0; ks < KDIM / 16; ++ks) {
        const int kb = ks * 16;
        uint32_t a[4], b[2][4];
        ldsm_x4_trans(a, sbase + FA + (kb + kl) * PA + (wm + ml) * 2);
        #pragma unroll
        for (int nb = 0; nb < 2; ++nb)
            ldsm_x4_trans(b[nb], sbase + FB + (kb + kl) * PB + (wn + nb * 16 + ml) * 2);
        #pragma unroll
        for (int nn = 0; nn < 4; ++nn) {
            const int nb = nn >> 1, sel = nn & 1;
            mma16816(acc[nn], a, b[nb][sel], b[nb][sel + 2]);
        }
    }

    // ---- fused epilogue: dw = acc*(LR/B) - (LR*WD)*W (W already in regs) ----
    const float c1 = 0.005f / 128.0f;
    const float c2 = 0.005f * 0.0001f;
    #pragma unroll
    for (int nn = 0; nn < 4; ++nn) {
        const int q = qcol + nn * 8;
        #pragma unroll
        for (int h = 0; h < 2; ++h) {
            const int p = prow + h * 8;
            float2 o;
            o.x = fmaf(acc[nn][2 * h + 0], c1, -c2 * wv[nn][h].x);
            o.y = fmaf(acc[nn][2 * h + 1], c1, -c2 * wv[nn][h].y);
            *(float2*)(out + (size_t)p * DIM + q) = o;
        }
    }
}

extern "C" void kernel_launch(void* const* d_in, const int* in_sizes, int n_in,
                              void* d_out, int out_size)
{
    const float* pre  = (const float*)d_in[0];   // (128, 1024)
    const float* post = (const float*)d_in[1];   // (128, 1024)
    const float* W    = (const float*)d_in[2];   // (1024, 1024)
    float* out = (float*)d_out;                  // (1024, 1024)

    static bool attr_set = false;
    if (!attr_set) {
        cudaFuncSetAttribute(hebbian_fused_kernel,
                             cudaFuncAttributeMaxDynamicSharedMemorySize, SMEM_TOTAL);
        attr_set = true;
    }
    dim3 grid(DIM / BN, DIM / BM);   // (16, 8) = 128 CTAs, all co-resident
    hebbian_fused_kernel<<<grid, NTHREADS, SMEM_TOTAL>>>(pre, post, W, out);
}

// round 12
// speedup vs baseline: 1.2132x; 1.2132x over previous
#include <cuda_runtime.h>
#include <cuda_fp16.h>
#include <cstdint>

// dw[p][q] = LR * ( (1/B)*sum_b post[b][p]*pre[b][q] - WD*W[p][q] )
// B=128, P=Q=1024.  fp16 single-pass mma.sync (rel err ~3e-5).
// R12: ONE launch. Conversion is layout-preserving (fp32 [k][m] -> fp16 [k][m])
// with fully coalesced LDG.128 along m and conflict-free STS.64; the m/k
// transpose happens for free inside ldmatrix.x4.trans (verified in R10).
// W prefetched into registers first; fused weight-decay epilogue.

#define DIM      1024
#define KDIM     128
#define NTHREADS 512
#define BM       128
#define BN       64

#define PA       272                  // A fp16 tile row pitch bytes (256 + 16 pad)
#define PB       144                  // B fp16 tile row pitch bytes (128 + 16 pad)
#define FA       0
#define FB       (KDIM * PA)          // 34816
#define SMEM_TOTAL (FB + KDIM * PB)   // 53248

static __device__ __forceinline__ uint32_t smem_u32(const void* p) {
    uint32_t a;
    asm("{ .reg .u64 t; cvta.to.shared.u64 t, %1; cvt.u32.u64 %0, t; }" : "=r"(a) : "l"(p));
    return a;
}
static __device__ __forceinline__ void ldsm_x4_trans(uint32_t* r, uint32_t addr) {
    asm volatile("ldmatrix.sync.aligned.m8n8.x4.trans.shared.b16 {%0,%1,%2,%3}, [%4];"
                 : "=r"(r[0]), "=r"(r[1]), "=r"(r[2]), "=r"(r[3]) : "r"(addr));
}
static __device__ __forceinline__ void mma16816(float* c, const uint32_t* a,
                                                uint32_t b0, uint32_t b1) {
    asm volatile(
        "mma.sync.aligned.m16n8k16.row.col.f32.f16.f16.f32 "
        "{%0,%1,%2,%3}, {%4,%5,%6,%7}, {%8,%9}, {%0,%1,%2,%3};"
        : "+f"(c[0]), "+f"(c[1]), "+f"(c[2]), "+f"(c[3])
        : "r"(a[0]), "r"(a[1]), "r"(a[2]), "r"(a[3]), "r"(b0), "r"(b1));
}
static __device__ __forceinline__ uint32_t pack_h2(float a, float b) {
    const __half2 h = __floats2half2_rn(a, b);
    return *(const uint32_t*)&h;
}

__global__ __launch_bounds__(NTHREADS, 1)
void hebbian_fp16_kernel(const float* __restrict__ pre,
                         const float* __restrict__ post,
                         const float* __restrict__ W,
                         float* __restrict__ out)
{
    extern __shared__ char smem[];
    const uint32_t sbase = smem_u32(smem);
    const int tid  = threadIdx.x;
    const int lane = tid & 31;
    const int wid  = tid >> 5;
    const int pm0  = blockIdx.y * BM;
    const int qn0  = blockIdx.x * BN;

    // warp tiling: 8(m) x 2(n), warp tile m16 x n32
    const int wm = (wid >> 1) * 16;
    const int wn = (wid & 1) * 32;
    const int prow = pm0 + wm + (lane >> 2);
    const int qcol = qn0 + wn + (lane & 3) * 2;

    // ---- issue W prefetch first (longest latency; drains during convert) ----
    float2 wv[4][2];
    #pragma unroll
    for (int nn = 0; nn < 4; ++nn) {
        const int q = qcol + nn * 8;
        wv[nn][0] = *(const float2*)(W + (size_t)prow * DIM + q);
        wv[nn][1] = *(const float2*)(W + (size_t)(prow + 8) * DIM + q);
    }

    // ---- issue ALL convert loads (coalesced LDG.128 along m), max MLP ----
    float4 va[8];                          // A: 128k x 32 groups = 4096 units
    #pragma unroll
    for (int it = 0; it < 8; ++it) {
        const int u = tid + NTHREADS * it;
        const int k = u >> 5;
        const int f = u & 31;
        va[it] = *(const float4*)(post + (size_t)k * DIM + pm0 + f * 4);
    }
    float4 vb[4];                          // B: 128k x 16 groups = 2048 units
    #pragma unroll
    for (int it = 0; it < 4; ++it) {
        const int u = tid + NTHREADS * it;
        const int k = u >> 4;
        const int f = u & 15;
        vb[it] = *(const float4*)(pre + (size_t)k * DIM + qn0 + f * 4);
    }

    // ---- convert + store fp16 tiles (layout-preserving, conflict-free) ----
    #pragma unroll
    for (int it = 0; it < 8; ++it) {
        const int u = tid + NTHREADS * it;
        const int k = u >> 5;
        const int f = u & 31;
        uint2 o;
        o.x = pack_h2(va[it].x, va[it].y);
        o.y = pack_h2(va[it].z, va[it].w);
        *(uint2*)(smem + FA + k * PA + f * 8) = o;
    }
    #pragma unroll
    for (int it = 0; it < 4; ++it) {
        const int u = tid + NTHREADS * it;
        const int k = u >> 4;
        const int f = u & 15;
        uint2 o;
        o.x = pack_h2(vb[it].x, vb[it].y);
        o.y = pack_h2(vb[it].z, vb[it].w);
        *(uint2*)(smem + FB + k * PB + f * 8) = o;
    }
    __syncthreads();

    // ---- mma mainloop (verified trans-ldmatrix scheme from R10) ----
    float acc[4][4];
    #pragma unroll
    for (int j = 0; j < 4; ++j)
        #pragma unroll
        for (int r = 0; r < 4; ++r)
            acc[j][r] = 0.0f;

    const int kl = (lane & 7) + ((lane >> 4) << 3);   // k row within 16-block
    const int ml = (lane & 8);                        // m/n sub-tile select

    #pragma unroll
    for (int ks = 0; ks < KDIM / 16; ++ks) {
        const int kb = ks * 16;
        uint32_t a[4], b[2][4];
        ldsm_x4_trans(a, sbase + FA + (kb + kl) * PA + (wm + ml) * 2);
        #pragma unroll
        for (int nb = 0; nb < 2; ++nb)
            ldsm_x4_trans(b[nb], sbase + FB + (kb + kl) * PB + (wn + nb * 16 + ml) * 2);
        #pragma unroll
        for (int nn = 0; nn < 4; ++nn) {
            const int nb = nn >> 1, sel = nn & 1;
            mma16816(acc[nn], a, b[nb][sel], b[nb][sel + 2]);
        }
    }

    // ---- fused epilogue: dw = acc*(LR/B) - (LR*WD)*W (W already in regs) ----
    const float c1 = 0.005f / 128.0f;
    const float c2 = 0.005f * 0.0001f;
    #pragma unroll
    for (int nn = 0; nn < 4; ++nn) {
        const int q = qcol + nn * 8;
        #pragma unroll
        for (int h = 0; h < 2; ++h) {
            const int p = prow + h * 8;
            float2 o;
            o.x = fmaf(acc[nn][2 * h + 0], c1, -c2 * wv[nn][h].x);
            o.y = fmaf(acc[nn][2 * h + 1], c1, -c2 * wv[nn][h].y);
            *(float2*)(out + (size_t)p * DIM + q) = o;
        }
    }
}

extern "C" void kernel_launch(void* const* d_in, const int* in_sizes, int n_in,
                              void* d_out, int out_size)
{
    const float* pre  = (const float*)d_in[0];   // (128, 1024)
    const float* post = (const float*)d_in[1];   // (128, 1024)
    const float* W    = (const float*)d_in[2];   // (1024, 1024)
    float* out = (float*)d_out;                  // (1024, 1024)

    static bool attr_set = false;
    if (!attr_set) {
        cudaFuncSetAttribute(hebbian_fp16_kernel,
                             cudaFuncAttributeMaxDynamicSharedMemorySize, SMEM_TOTAL);
        attr_set = true;
    }
    dim3 grid(DIM / BN, DIM / BM);   // (16, 8) = 128 CTAs, 1/SM, single wave
    hebbian_fp16_kernel<<<grid, NTHREADS, SMEM_TOTAL>>>(pre, post, W, out);
}

// round 13
// speedup vs baseline: 1.2177x; 1.0037x over previous
#include <cuda_runtime.h>
#include <cuda_fp16.h>
#include <cstdint>

// dw[p][q] = LR * ( (1/B)*sum_b post[b][p]*pre[b][q] - WD*W[p][q] )
// B=128, P=Q=1024.  fp16 single-pass mma.sync (rel err ~3e-5).
// R13: 64x64 tiles, 256 CTAs, 2 CTAs/SM co-resident -> cross-CTA phase
// overlap (one CTA's convert/epilogue hides the other's barrier + LDSM->MMA
// chains). Convert is layout-preserving coalesced LDG.128 + F2FP + STS.64;
// transpose happens inside ldmatrix.x4.trans (verified R10/R12 scheme).

#define DIM      1024
#define KDIM     128
#define NTHREADS 256
#define BM       64
#define BN       64

#define PA       144                  // fp16 tile row pitch bytes (128 data + 16 pad)
#define PB       144
#define FA       0
#define FB       (KDIM * PA)          // 18432
#define SMEM_TOTAL (2 * KDIM * PA)    // 36864 B -> 2 CTAs/SM

static __device__ __forceinline__ uint32_t smem_u32(const void* p) {
    uint32_t a;
    asm("{ .reg .u64 t; cvta.to.shared.u64 t, %1; cvt.u32.u64 %0, t; }" : "=r"(a) : "l"(p));
    return a;
}
static __device__ __forceinline__ void ldsm_x4_trans(uint32_t* r, uint32_t addr) {
    asm volatile("ldmatrix.sync.aligned.m8n8.x4.trans.shared.b16 {%0,%1,%2,%3}, [%4];"
                 : "=r"(r[0]), "=r"(r[1]), "=r"(r[2]), "=r"(r[3]) : "r"(addr));
}
static __device__ __forceinline__ void mma16816(float* c, const uint32_t* a,
                                                uint32_t b0, uint32_t b1) {
    asm volatile(
        "mma.sync.aligned.m16n8k16.row.col.f32.f16.f16.f32 "
        "{%0,%1,%2,%3}, {%4,%5,%6,%7}, {%8,%9}, {%0,%1,%2,%3};"
        : "+f"(c[0]), "+f"(c[1]), "+f"(c[2]), "+f"(c[3])
        : "r"(a[0]), "r"(a[1]), "r"(a[2]), "r"(a[3]), "r"(b0), "r"(b1));
}
static __device__ __forceinline__ uint32_t pack_h2(float a, float b) {
    const __half2 h = __floats2half2_rn(a, b);
    return *(const uint32_t*)&h;
}

__global__ __launch_bounds__(NTHREADS, 2)
void hebbian_fp16_kernel(const float* __restrict__ pre,
                         const float* __restrict__ post,
                         const float* __restrict__ W,
                         float* __restrict__ out)
{
    extern __shared__ char smem[];
    const uint32_t sbase = smem_u32(smem);
    const int tid  = threadIdx.x;
    const int lane = tid & 31;
    const int wid  = tid >> 5;
    const int pm0  = blockIdx.y * BM;
    const int qn0  = blockIdx.x * BN;

    // warp tiling: 4(m) x 2(n) warps, warp tile m16 x n32
    const int wm = (wid >> 1) * 16;
    const int wn = (wid & 1) * 32;
    const int prow = pm0 + wm + (lane >> 2);
    const int qcol = qn0 + wn + (lane & 3) * 2;

    // ---- issue W prefetch first (longest latency; drains during convert) ----
    float2 wv[4][2];
    #pragma unroll
    for (int nn = 0; nn < 4; ++nn) {
        const int q = qcol + nn * 8;
        wv[nn][0] = *(const float2*)(W + (size_t)prow * DIM + q);
        wv[nn][1] = *(const float2*)(W + (size_t)(prow + 8) * DIM + q);
    }

    // ---- issue ALL convert loads (coalesced LDG.128 along m), max MLP ----
    // A: 128 k-rows x 16 float4 groups = 2048 units; 8/thread. B likewise.
    float4 va[8], vb[8];
    #pragma unroll
    for (int it = 0; it < 8; ++it) {
        const int u = tid + NTHREADS * it;
        const int k = u >> 4;
        const int f = u & 15;
        va[it] = *(const float4*)(post + (size_t)k * DIM + pm0 + f * 4);
        vb[it] = *(const float4*)(pre  + (size_t)k * DIM + qn0 + f * 4);
    }

    // ---- convert + store fp16 tiles (layout-preserving, conflict-free) ----
    #pragma unroll
    for (int it = 0; it < 8; ++it) {
        const int u = tid + NTHREADS * it;
        const int k = u >> 4;
        const int f = u & 15;
        uint2 oa, ob;
        oa.x = pack_h2(va[it].x, va[it].y); oa.y = pack_h2(va[it].z, va[it].w);
        ob.x = pack_h2(vb[it].x, vb[it].y); ob.y = pack_h2(vb[it].z, vb[it].w);
        *(uint2*)(smem + FA + k * PA + f * 8) = oa;
        *(uint2*)(smem + FB + k * PB + f * 8) = ob;
    }
    __syncthreads();

    // ---- mma mainloop (verified trans-ldmatrix scheme) ----
    float acc[4][4];
    #pragma unroll
    for (int j = 0; j < 4; ++j)
        #pragma unroll
        for (int r = 0; r < 4; ++r)
            acc[j][r] = 0.0f;

    const int kl = (lane & 7) + ((lane >> 4) << 3);   // k row within 16-block
    const int ml = (lane & 8);                        // m/n sub-tile select

    #pragma unroll
    for (int ks = 0; ks < KDIM / 16; ++ks) {
        const int kb = ks * 16;
        uint32_t a[4], b[2][4];
        ldsm_x4_trans(a, sbase + FA + (kb + kl) * PA + (wm + ml) * 2);
        #pragma unroll
        for (int nb = 0; nb < 2; ++nb)
            ldsm_x4_trans(b[nb], sbase + FB + (kb + kl) * PB + (wn + nb * 16 + ml) * 2);
        #pragma unroll
        for (int nn = 0; nn < 4; ++nn) {
            const int nb = nn >> 1, sel = nn & 1;
            mma16816(acc[nn], a, b[nb][sel], b[nb][sel + 2]);
        }
    }

    // ---- fused epilogue: dw = acc*(LR/B) - (LR*WD)*W (W already in regs) ----
    const float c1 = 0.005f / 128.0f;
    const float c2 = 0.005f * 0.0001f;
    #pragma unroll
    for (int nn = 0; nn < 4; ++nn) {
        const int q = qcol + nn * 8;
        #pragma unroll
        for (int h = 0; h < 2; ++h) {
            const int p = prow + h * 8;
            float2 o;
            o.x = fmaf(acc[nn][2 * h + 0], c1, -c2 * wv[nn][h].x);
            o.y = fmaf(acc[nn][2 * h + 1], c1, -c2 * wv[nn][h].y);
            *(float2*)(out + (size_t)p * DIM + q) = o;
        }
    }
}

extern "C" void kernel_launch(void* const* d_in, const int* in_sizes, int n_in,
                              void* d_out, int out_size)
{
    const float* pre  = (const float*)d_in[0];   // (128, 1024)
    const float* post = (const float*)d_in[1];   // (128, 1024)
    const float* W    = (const float*)d_in[2];   // (1024, 1024)
    float* out = (float*)d_out;                  // (1024, 1024)

    static bool attr_set = false;
    if (!attr_set) {
        cudaFuncSetAttribute(hebbian_fp16_kernel,
                             cudaFuncAttributeMaxDynamicSharedMemorySize, SMEM_TOTAL);
        attr_set = true;
    }
    dim3 grid(DIM / BN, DIM / BM);   // (16, 16) = 256 CTAs, 2/SM co-resident
    hebbian_fp16_kernel<<<grid, NTHREADS, SMEM_TOTAL>>>(pre, post, W, out);
}